// round 15
// baseline (speedup 1.0000x reference)
#include <cuda_runtime.h>
#include <cuda_bf16.h>
#include <cstdint>
#include <cstddef>

#define B_   32
#define T_   512
#define H_   512
#define D_   512
#define SIXH 3072
#define BH   (B_ * H_)

#define NBLK 128
#define CPB  8
#define BGRP 16
#define NROW 40
#define SSTR 520
#define PSTR 44
#define NTHR 256
#define GTILES 3072          // 128 m-tiles x 24 n-tiles
#define NX4 ((B_ * T_ * D_) / 4)
#define NW4 ((SIXH * D_) / 4)

// Scratch (device globals)
__device__ float         g_pi[(size_t)B_ * T_ * SIXH];     // rows m = t*32 + b
__device__ uint32_t      g_hfrag[2][2][2][4096];
__device__ unsigned      g_flag[2][8][8];                  // [group][sub][slot] = steps published
__device__ unsigned      g_piprog[128];                    // n-tiles done per m-tile
__device__ __nv_bfloat16 g_xhi[(size_t)B_ * T_ * D_];
__device__ __nv_bfloat16 g_xlo[(size_t)B_ * T_ * D_];
__device__ __nv_bfloat16 g_whi[(size_t)SIXH * D_];
__device__ __nv_bfloat16 g_wlo[(size_t)SIXH * D_];

__global__ void init_k() {
    int i = threadIdx.x;
    if (i < 128) g_piprog[i] = 0u;
    if (i < 128) ((unsigned*)g_flag)[i] = 0u;
}

// ---------------------------------------------------------------------------
__device__ __forceinline__ void split4(const float* __restrict__ src,
                                       __nv_bfloat16* __restrict__ hi,
                                       __nv_bfloat16* __restrict__ lo, int i) {
    float4 f = ((const float4*)src)[i];
    __nv_bfloat16 h0 = __float2bfloat16(f.x);
    __nv_bfloat16 h1 = __float2bfloat16(f.y);
    __nv_bfloat16 h2 = __float2bfloat16(f.z);
    __nv_bfloat16 h3 = __float2bfloat16(f.w);
    __nv_bfloat162 hv0, hv1, lv0, lv1;
    hv0.x = h0; hv0.y = h1; hv1.x = h2; hv1.y = h3;
    lv0.x = __float2bfloat16(f.x - __bfloat162float(h0));
    lv0.y = __float2bfloat16(f.y - __bfloat162float(h1));
    lv1.x = __float2bfloat16(f.z - __bfloat162float(h2));
    lv1.y = __float2bfloat16(f.w - __bfloat162float(h3));
    ((__nv_bfloat162*)hi)[2 * i]     = hv0;
    ((__nv_bfloat162*)hi)[2 * i + 1] = hv1;
    ((__nv_bfloat162*)lo)[2 * i]     = lv0;
    ((__nv_bfloat162*)lo)[2 * i + 1] = lv1;
}

// Single merged split kernel: x range then Wi range.
__global__ void split_all_k(const float* __restrict__ x,
                            const float* __restrict__ Wi) {
    int i = blockIdx.x * blockDim.x + threadIdx.x;
    if (i < NX4)            split4(x,  g_xhi, g_xlo, i);
    else if (i < NX4 + NW4) split4(Wi, g_whi, g_wlo, i - NX4);
}

// ---------------------------------------------------------------------------
__device__ __forceinline__ void ldsm_x4(uint32_t& r0, uint32_t& r1,
                                        uint32_t& r2, uint32_t& r3, uint32_t a) {
    asm volatile("ldmatrix.sync.aligned.m8n8.x4.shared.b16 {%0,%1,%2,%3}, [%4];"
                 : "=r"(r0), "=r"(r1), "=r"(r2), "=r"(r3) : "r"(a));
}
__device__ __forceinline__ void ldsm_x2(uint32_t& r0, uint32_t& r1, uint32_t a) {
    asm volatile("ldmatrix.sync.aligned.m8n8.x2.shared.b16 {%0,%1}, [%2];"
                 : "=r"(r0), "=r"(r1) : "r"(a));
}
__device__ __forceinline__ void mma16816(float* c, const uint32_t* a,
                                         uint32_t b0, uint32_t b1) {
    asm volatile(
        "mma.sync.aligned.m16n8k16.row.col.f32.bf16.bf16.f32 "
        "{%0,%1,%2,%3},{%4,%5,%6,%7},{%8,%9},{%0,%1,%2,%3};"
        : "+f"(c[0]), "+f"(c[1]), "+f"(c[2]), "+f"(c[3])
        : "r"(a[0]), "r"(a[1]), "r"(a[2]), "r"(a[3]), "r"(b0), "r"(b1));
}
__device__ __forceinline__ void cpa16(uint32_t dst, const void* src) {
    asm volatile("cp.async.cg.shared.global [%0], [%1], 16;"
                 :: "r"(dst), "l"(src));
}
__device__ __forceinline__ void cpa_commit() {
    asm volatile("cp.async.commit_group;");
}
__device__ __forceinline__ uint32_t ldcg32(const void* p) {
    uint32_t v;
    asm volatile("ld.global.cg.b32 %0, [%1];" : "=r"(v) : "l"(p));
    return v;
}
__device__ __forceinline__ float ldcgf(const float* p) {
    float v;
    asm volatile("ld.global.cg.f32 %0, [%1];" : "=f"(v) : "l"(p));
    return v;
}

__device__ __forceinline__ float sigm(float x)  { return 1.f / (1.f + __expf(-x)); }
__device__ __forceinline__ float tanh_(float x) { return 1.f - 2.f / (__expf(2.f * x) + 1.f); }

__device__ __forceinline__ void wait_pi(int mt) {
    if ((threadIdx.x & 31) == 0) {
        while (*(volatile unsigned*)&g_piprog[mt] < 24u) __nanosleep(64);
    }
    __syncwarp();
}

// ---------------------------------------------------------------------------
// Fused kernel: blocks [0,128) = persistent scan; [128, 128+3072) = GEMM tiles.
// ---------------------------------------------------------------------------
#define ASTR2  80
#define STAGE2 (4 * 128 * ASTR2)   // 40960 B per stage (2 stages = 81920)

__global__ __launch_bounds__(256, 2) void fused_k(
    const float* __restrict__ bi, const float* __restrict__ Ws,
    const float* __restrict__ bs, const int* __restrict__ lengths,
    float* __restrict__ out)
{
    extern __shared__ char smc[];
    const int tid  = threadIdx.x;
    const int lane = tid & 31;
    const int warp = tid >> 5;

    if (blockIdx.x >= NBLK) {
        // =================== GEMM tile ===================
        const int g   = blockIdx.x - NBLK;
        const int mt  = g / 24;
        const int nt  = g - mt * 24;
        const int m0  = mt * 128;
        const int n0  = nt * 128;

        const int wm = warp >> 2;
        const int wn = warp & 3;

        const int lrow  = tid >> 1;
        const int lhalf = tid & 1;
        const int m     = m0 + lrow;
        const int xrow  = (m & 31) * T_ + (m >> 5);    // x[b][t] source row
        const __nv_bfloat16* pxh = g_xhi + (size_t)xrow * D_;
        const __nv_bfloat16* pxl = g_xlo + (size_t)xrow * D_;
        const __nv_bfloat16* pwh = g_whi + (size_t)(n0 + lrow) * D_;
        const __nv_bfloat16* pwl = g_wlo + (size_t)(n0 + lrow) * D_;

        const uint32_t sbase = (uint32_t)__cvta_generic_to_shared(smc);
        const uint32_t stoff = lrow * ASTR2 + lhalf * 32;

        const int rowA = wm * 64 + (lane & 15);
        const uint32_t aAh0 = sbase + rowA * ASTR2 + (lane >> 4) * 16;
        const uint32_t aAl0 = aAh0 + 128 * ASTR2;
        const int rowB = wn * 32 + (lane & 7) + ((lane >> 4) << 3);
        const uint32_t aBh0 = sbase + 2 * 128 * ASTR2 + rowB * ASTR2 + ((lane >> 3) & 1) * 16;
        const uint32_t aBl0 = aBh0 + 128 * ASTR2;

        float acc[4][4][4];
#pragma unroll
        for (int i = 0; i < 4; i++)
#pragma unroll
            for (int j = 0; j < 4; j++)
#pragma unroll
                for (int e = 0; e < 4; e++) acc[i][j][e] = 0.f;

        auto commit_stage = [&](int p, int kts) {
            uint32_t d = sbase + p * STAGE2 + stoff;
            const int ko = kts * 32 + lhalf * 16;
            cpa16(d,                        pxh + ko);
            cpa16(d + 16,                   pxh + ko + 8);
            cpa16(d +     128 * ASTR2,      pxl + ko);
            cpa16(d +     128 * ASTR2 + 16, pxl + ko + 8);
            cpa16(d + 2 * 128 * ASTR2,      pwh + ko);
            cpa16(d + 2 * 128 * ASTR2 + 16, pwh + ko + 8);
            cpa16(d + 3 * 128 * ASTR2,      pwl + ko);
            cpa16(d + 3 * 128 * ASTR2 + 16, pwl + ko + 8);
            cpa_commit();
        };

        commit_stage(0, 0);

        for (int kts = 0; kts < 16; kts++) {
            asm volatile("cp.async.wait_group 0;");
            __syncthreads();
            if (kts + 1 < 16) commit_stage((kts + 1) & 1, kts + 1);

            const uint32_t po = (kts & 1) * STAGE2;
#pragma unroll
            for (int kk = 0; kk < 2; kk++) {
                const uint32_t kko = po + kk * 32;
                uint32_t ah[4][4], al[4][4], bh[4][2], bl[4][2];
#pragma unroll
                for (int mi = 0; mi < 4; mi++) {
                    ldsm_x4(ah[mi][0], ah[mi][1], ah[mi][2], ah[mi][3],
                            aAh0 + kko + mi * 16 * ASTR2);
                    ldsm_x4(al[mi][0], al[mi][1], al[mi][2], al[mi][3],
                            aAl0 + kko + mi * 16 * ASTR2);
                }
#pragma unroll
                for (int bg = 0; bg < 2; bg++) {
                    ldsm_x4(bh[2 * bg][0], bh[2 * bg][1], bh[2 * bg + 1][0], bh[2 * bg + 1][1],
                            aBh0 + kko + bg * 16 * ASTR2);
                    ldsm_x4(bl[2 * bg][0], bl[2 * bg][1], bl[2 * bg + 1][0], bl[2 * bg + 1][1],
                            aBl0 + kko + bg * 16 * ASTR2);
                }
#pragma unroll
                for (int mi = 0; mi < 4; mi++)
#pragma unroll
                    for (int ni = 0; ni < 4; ni++) {
                        mma16816(acc[mi][ni], ah[mi], bh[ni][0], bh[ni][1]);
                        mma16816(acc[mi][ni], ah[mi], bl[ni][0], bl[ni][1]);
                        mma16816(acc[mi][ni], al[mi], bh[ni][0], bh[ni][1]);
                    }
            }
        }

#pragma unroll
        for (int ni = 0; ni < 4; ni++) {
            const int n = n0 + wn * 32 + ni * 8 + 2 * (lane & 3);
            float b0 = bi[n], b1 = bi[n + 1];
#pragma unroll
            for (int mi = 0; mi < 4; mi++) {
                const int mm = m0 + wm * 64 + mi * 16 + (lane >> 2);
                float* C0 = g_pi + (size_t)mm * SIXH + n;
                float* C1 = g_pi + (size_t)(mm + 8) * SIXH + n;
                *(float2*)C0 = make_float2(acc[mi][ni][0] + b0, acc[mi][ni][1] + b1);
                *(float2*)C1 = make_float2(acc[mi][ni][2] + b0, acc[mi][ni][3] + b1);
            }
        }
        __threadfence();
        __syncthreads();
        if (tid == 0) atomicAdd(&g_piprog[mt], 1u);
        return;
    }

    // =================== persistent scan ===================
    __nv_bfloat16* sWh   = (__nv_bfloat16*)smc;          // NROW x SSTR
    __nv_bfloat16* sWl   = sWh + NROW * SSTR;            // NROW x SSTR
    float*         sPart = (float*)(sWl + NROW * SSTR);  // 8 x 16 x PSTR

    const int blk   = blockIdx.x;
    const int group = blk >> 6;
    const int cb    = blk & 63;
    const int sub   = cb >> 3;
    const int slot  = cb & 7;
    const int kh    = warp;

    // Ws -> smem bf16 split
    for (int i = tid; i < NROW * (H_ / 8); i += NTHR) {
        int l  = i >> 6;
        int d8 = (i & 63) << 3;
        __nv_bfloat16* ph = sWh + l * SSTR + d8;
        __nv_bfloat16* pl = sWl + l * SSTR + d8;
        int row = (l >> 3) * H_ + cb * CPB + (l & 7);
        const float* p = Ws + (size_t)row * H_ + d8;
#pragma unroll
        for (int q = 0; q < 8; q++) {
            float f = p[q];
            __nv_bfloat16 hh = __float2bfloat16(f);
            ph[q] = hh;
            pl[q] = __float2bfloat16(f - __bfloat162float(hh));
        }
    }

    const uint32_t aBh = (uint32_t)__cvta_generic_to_shared(
        sWh + (size_t)(lane & 7) * SSTR) + ((lane >> 3) & 1) * 16 + kh * 128;
    const uint32_t aBl = aBh + NROW * SSTR * 2;

    float c_reg = 0.f, h_reg = 0.f;
    float bsv[5] = {0.f, 0.f, 0.f, 0.f, 0.f};
    int bg = 0, j0 = 0, len = 0, b_local = 0, fo = 0;
    if (tid < 128) {
        b_local = tid >> 3;
        bg = group * BGRP + b_local;
        j0 = cb * CPB + (tid & 7);
        len = lengths[bg];
#pragma unroll
        for (int g = 0; g < 5; g++) bsv[g] = bs[g * H_ + j0];
        {
            const int c    = j0;
            const int frag = ((c >> 3) & 1) * 2 + (b_local >> 3);
            const int ln   = ((b_local & 7) << 2) | ((c >> 1) & 3);
            const int word = (((c >> 6) * 4 + ((c >> 4) & 3)) * 4 + frag) * 32 + ln;
            fo = word * 2 + (c & 1);
        }
        __stcg((unsigned short*)g_hfrag[0][0][group] + fo, (unsigned short)0);
        __stcg((unsigned short*)g_hfrag[1][0][group] + fo, (unsigned short)0);
        __threadfence();
    }
    __syncthreads();
    if (tid == 0) *(volatile unsigned*)&g_flag[group][sub][slot] = 1u;   // h0 published

    const volatile unsigned* fptr = &g_flag[group][kh][0];

    float pv_cur[6] = {0,0,0,0,0,0}, pv_nxt[6] = {0,0,0,0,0,0};
    const float* ppi = (tid < 128) ? g_pi + (size_t)bg * SIXH + j0 : g_pi;  // row t*32+bg
    if (tid < 128) {
        wait_pi(0);
#pragma unroll
        for (int g = 0; g < 6; g++) pv_cur[g] = ldcgf(ppi + g * H_);
    }

    for (int t = 0; t < T_; t++) {
        if (tid < 128 && t + 1 < T_) {
            if (((t + 1) & 3) == 0) wait_pi((t + 1) >> 2);
            const float* pp = ppi + (size_t)(t + 1) * (32 * SIXH);
#pragma unroll
            for (int g = 0; g < 6; g++) pv_nxt[g] = ldcgf(pp + g * H_);
        }

        // poll my chunk's 8 writer flags (one 32B sector, lanes 0-7)
        {
            const unsigned need = (unsigned)(t + 1);
            if (lane < 8) {
                while (fptr[lane] < need) {}
            }
            __syncwarp();
        }

        const uint32_t* bh_ = &g_hfrag[0][t & 1][group][kh * 512 + lane];
        const uint32_t* bl_ = &g_hfrag[1][t & 1][group][kh * 512 + lane];
        uint32_t Ah[4][4], Al[4][4];
#pragma unroll
        for (int kk = 0; kk < 4; kk++)
#pragma unroll
            for (int fr = 0; fr < 4; fr++) {
                Ah[kk][fr] = ldcg32(bh_ + (kk * 4 + fr) * 32);
                Al[kk][fr] = ldcg32(bl_ + (kk * 4 + fr) * 32);
            }

        {
            float acc[5][4];
#pragma unroll
            for (int ni = 0; ni < 5; ni++)
#pragma unroll
                for (int e = 0; e < 4; e++) acc[ni][e] = 0.f;
#pragma unroll
            for (int kk = 0; kk < 4; kk++) {
                const uint32_t ko = kk * 32;
#pragma unroll
                for (int ni = 0; ni < 5; ni++) {
                    const uint32_t bo = ko + ni * 8 * SSTR * 2;
                    uint32_t b0h, b1h, b0l, b1l;
                    ldsm_x2(b0h, b1h, aBh + bo);
                    ldsm_x2(b0l, b1l, aBl + bo);
                    mma16816(acc[ni], Ah[kk], b0h, b1h);
                    mma16816(acc[ni], Al[kk], b0h, b1h);
                    mma16816(acc[ni], Ah[kk], b0l, b1l);
                }
            }
            float* pp = sPart + kh * 16 * PSTR;
            const int r = lane >> 2;
#pragma unroll
            for (int ni = 0; ni < 5; ni++) {
                const int n = ni * 8 + 2 * (lane & 3);
                *(float2*)&pp[r * PSTR + n]       = make_float2(acc[ni][0], acc[ni][1]);
                *(float2*)&pp[(r + 8) * PSTR + n] = make_float2(acc[ni][2], acc[ni][3]);
            }
        }
        __syncthreads();

        if (tid < 128) {
            const int jj = tid & 7;
            float ps[5];
#pragma unroll
            for (int g = 0; g < 5; g++) {
                float s = 0.f;
#pragma unroll
                for (int w = 0; w < 8; w++)
                    s += sPart[w * 16 * PSTR + b_local * PSTR + g * 8 + jj];
                ps[g] = s + bsv[g];
            }
            float iv = sigm(pv_cur[0] + ps[0]);
            float fv = sigm(pv_cur[1] + ps[1]);
            float gv = tanh_(pv_cur[2] + ps[2]);
            float ov = sigm(pv_cur[3] + ps[3]);
            float cn = iv * gv + fv * c_reg;
            float o1 = ov * tanh_(cn);
            float rv = sigm(pv_cur[4] + ps[4]);
            float o2 = rv * o1 + (1.f - rv) * pv_cur[5];
            bool  m  = (t < len);
            h_reg = m ? o2 : h_reg;
            c_reg = m ? cn : c_reg;
            __nv_bfloat16 hh = __float2bfloat16(h_reg);
            __nv_bfloat16 hl = __float2bfloat16(h_reg - __bfloat162float(hh));
            const int par = (t + 1) & 1;
            __stcg((unsigned short*)g_hfrag[0][par][group] + fo, __bfloat16_as_ushort(hh));
            __stcg((unsigned short*)g_hfrag[1][par][group] + fo, __bfloat16_as_ushort(hl));
            out[((size_t)bg * T_ + t) * H_ + j0] = m ? o2 : 0.f;
            if (t == T_ - 1) {
                out[(size_t)B_ * T_ * H_ + bg * H_ + j0]      = h_reg;
                out[(size_t)B_ * T_ * H_ + BH + bg * H_ + j0] = c_reg;
            }
            __threadfence();
        }
#pragma unroll
        for (int g = 0; g < 6; g++) pv_cur[g] = pv_nxt[g];

        __syncthreads();       // all h stores + fences complete before flag store
        if (tid == 0) *(volatile unsigned*)&g_flag[group][sub][slot] = (unsigned)(t + 2);
    }
}

// ---------------------------------------------------------------------------
extern "C" void kernel_launch(void* const* d_in, const int* in_sizes, int n_in,
                              void* d_out, int out_size) {
    const float* x       = (const float*)d_in[0];
    const int*   lengths = (const int*)  d_in[1];
    const float* Wi      = (const float*)d_in[2];
    const float* bi      = (const float*)d_in[3];
    const float* Ws      = (const float*)d_in[4];
    const float* bs      = (const float*)d_in[5];
    float* out = (float*)d_out;

    const int smem = 2 * NROW * SSTR * 2 + 8 * 16 * PSTR * 4;   // 105,728 B
    cudaFuncSetAttribute(fused_k, cudaFuncAttributeMaxDynamicSharedMemorySize, smem);

    init_k<<<1, 128>>>();
    split_all_k<<<(NX4 + NW4 + 255) / 256, 256>>>(x, Wi);
    fused_k<<<NBLK + GTILES, NTHR, smem>>>(bi, Ws, bs, lengths, out);
}

// round 16
// speedup vs baseline: 1.8940x; 1.8940x over previous
#include <cuda_runtime.h>
#include <cuda_bf16.h>
#include <cstdint>
#include <cstddef>

#define B_   32
#define T_   512
#define H_   512
#define D_   512
#define SIXH 3072
#define BH   (B_ * H_)

#define NBLK 128
#define CPB  8
#define BGRP 16
#define NROW 40
#define SSTR 520
#define PSTR 44
#define NTHR 256
#define GTILES 3072          // 128 m-tiles x 24 n-tiles
#define NX4 ((B_ * T_ * D_) / 4)
#define NW4 ((SIXH * D_) / 4)

// Scratch (device globals)
__device__ float         g_pi[(size_t)B_ * T_ * SIXH];     // rows m = t*32 + b
__device__ uint32_t      g_hfrag[2][2][2][4096];
__device__ unsigned      g_cnt[2][8];
__device__ unsigned      g_piprog[128];                    // n-tiles done per m-tile
__device__ __nv_bfloat16 g_xhi[(size_t)B_ * T_ * D_];
__device__ __nv_bfloat16 g_xlo[(size_t)B_ * T_ * D_];
__device__ __nv_bfloat16 g_whi[(size_t)SIXH * D_];
__device__ __nv_bfloat16 g_wlo[(size_t)SIXH * D_];

// ---------------------------------------------------------------------------
__device__ __forceinline__ void split4(const float* __restrict__ src,
                                       __nv_bfloat16* __restrict__ hi,
                                       __nv_bfloat16* __restrict__ lo, int i) {
    float4 f = ((const float4*)src)[i];
    __nv_bfloat16 h0 = __float2bfloat16(f.x);
    __nv_bfloat16 h1 = __float2bfloat16(f.y);
    __nv_bfloat16 h2 = __float2bfloat16(f.z);
    __nv_bfloat16 h3 = __float2bfloat16(f.w);
    __nv_bfloat162 hv0, hv1, lv0, lv1;
    hv0.x = h0; hv0.y = h1; hv1.x = h2; hv1.y = h3;
    lv0.x = __float2bfloat16(f.x - __bfloat162float(h0));
    lv0.y = __float2bfloat16(f.y - __bfloat162float(h1));
    lv1.x = __float2bfloat16(f.z - __bfloat162float(h2));
    lv1.y = __float2bfloat16(f.w - __bfloat162float(h3));
    ((__nv_bfloat162*)hi)[2 * i]     = hv0;
    ((__nv_bfloat162*)hi)[2 * i + 1] = hv1;
    ((__nv_bfloat162*)lo)[2 * i]     = lv0;
    ((__nv_bfloat162*)lo)[2 * i + 1] = lv1;
}

// Single prologue kernel: init flags (block 0) + split x and Wi.
__global__ void split_all_k(const float* __restrict__ x,
                            const float* __restrict__ Wi) {
    if (blockIdx.x == 0) {
        int j = threadIdx.x;
        if (j < 128) g_piprog[j] = 0u;
        if (j < 16) ((unsigned*)g_cnt)[j] = 0u;
    }
    int i = blockIdx.x * blockDim.x + threadIdx.x;
    if (i < NX4)            split4(x,  g_xhi, g_xlo, i);
    else if (i < NX4 + NW4) split4(Wi, g_whi, g_wlo, i - NX4);
}

// ---------------------------------------------------------------------------
__device__ __forceinline__ void ldsm_x4(uint32_t& r0, uint32_t& r1,
                                        uint32_t& r2, uint32_t& r3, uint32_t a) {
    asm volatile("ldmatrix.sync.aligned.m8n8.x4.shared.b16 {%0,%1,%2,%3}, [%4];"
                 : "=r"(r0), "=r"(r1), "=r"(r2), "=r"(r3) : "r"(a));
}
__device__ __forceinline__ void ldsm_x2(uint32_t& r0, uint32_t& r1, uint32_t a) {
    asm volatile("ldmatrix.sync.aligned.m8n8.x2.shared.b16 {%0,%1}, [%2];"
                 : "=r"(r0), "=r"(r1) : "r"(a));
}
__device__ __forceinline__ void mma16816(float* c, const uint32_t* a,
                                         uint32_t b0, uint32_t b1) {
    asm volatile(
        "mma.sync.aligned.m16n8k16.row.col.f32.bf16.bf16.f32 "
        "{%0,%1,%2,%3},{%4,%5,%6,%7},{%8,%9},{%0,%1,%2,%3};"
        : "+f"(c[0]), "+f"(c[1]), "+f"(c[2]), "+f"(c[3])
        : "r"(a[0]), "r"(a[1]), "r"(a[2]), "r"(a[3]), "r"(b0), "r"(b1));
}
__device__ __forceinline__ void cpa16(uint32_t dst, const void* src) {
    asm volatile("cp.async.cg.shared.global [%0], [%1], 16;"
                 :: "r"(dst), "l"(src));
}
__device__ __forceinline__ void cpa_commit() {
    asm volatile("cp.async.commit_group;");
}
__device__ __forceinline__ uint32_t ldcg32(const void* p) {
    uint32_t v;
    asm volatile("ld.global.cg.b32 %0, [%1];" : "=r"(v) : "l"(p));
    return v;
}
__device__ __forceinline__ float ldcgf(const float* p) {
    float v;
    asm volatile("ld.global.cg.f32 %0, [%1];" : "=f"(v) : "l"(p));
    return v;
}

__device__ __forceinline__ float sigm(float x)  { return 1.f / (1.f + __expf(-x)); }
__device__ __forceinline__ float tanh_(float x) { return 1.f - 2.f / (__expf(2.f * x) + 1.f); }

__device__ __forceinline__ void wait_pi(int mt) {
    if ((threadIdx.x & 31) == 0) {
        while (*(volatile unsigned*)&g_piprog[mt] < 24u) __nanosleep(64);
    }
    __syncwarp();
}

// ---------------------------------------------------------------------------
// Fused kernel (EXACT R13): [0,128) persistent scan; [128, 128+3072) GEMM tiles.
// GEMM tiles m-tile-major so pi becomes ready in scan consumption order.
// ---------------------------------------------------------------------------
#define ASTR2  80
#define STAGE2 (4 * 128 * ASTR2)   // 40960 B per stage (2 stages = 81920)

__global__ __launch_bounds__(256, 2) void fused_k(
    const float* __restrict__ bi, const float* __restrict__ Ws,
    const float* __restrict__ bs, const int* __restrict__ lengths,
    float* __restrict__ out)
{
    extern __shared__ char smc[];
    const int tid  = threadIdx.x;
    const int lane = tid & 31;
    const int warp = tid >> 5;

    if (blockIdx.x >= NBLK) {
        // =================== GEMM tile ===================
        const int g   = blockIdx.x - NBLK;
        const int mt  = g / 24;
        const int nt  = g - mt * 24;
        const int m0  = mt * 128;
        const int n0  = nt * 128;

        const int wm = warp >> 2;
        const int wn = warp & 3;

        const int lrow  = tid >> 1;
        const int lhalf = tid & 1;
        const int m     = m0 + lrow;
        const int xrow  = (m & 31) * T_ + (m >> 5);    // x[b][t] source row
        const __nv_bfloat16* pxh = g_xhi + (size_t)xrow * D_;
        const __nv_bfloat16* pxl = g_xlo + (size_t)xrow * D_;
        const __nv_bfloat16* pwh = g_whi + (size_t)(n0 + lrow) * D_;
        const __nv_bfloat16* pwl = g_wlo + (size_t)(n0 + lrow) * D_;

        const uint32_t sbase = (uint32_t)__cvta_generic_to_shared(smc);
        const uint32_t stoff = lrow * ASTR2 + lhalf * 32;

        const int rowA = wm * 64 + (lane & 15);
        const uint32_t aAh0 = sbase + rowA * ASTR2 + (lane >> 4) * 16;
        const uint32_t aAl0 = aAh0 + 128 * ASTR2;
        const int rowB = wn * 32 + (lane & 7) + ((lane >> 4) << 3);
        const uint32_t aBh0 = sbase + 2 * 128 * ASTR2 + rowB * ASTR2 + ((lane >> 3) & 1) * 16;
        const uint32_t aBl0 = aBh0 + 128 * ASTR2;

        float acc[4][4][4];
#pragma unroll
        for (int i = 0; i < 4; i++)
#pragma unroll
            for (int j = 0; j < 4; j++)
#pragma unroll
                for (int e = 0; e < 4; e++) acc[i][j][e] = 0.f;

        auto commit_stage = [&](int p, int kts) {
            uint32_t d = sbase + p * STAGE2 + stoff;
            const int ko = kts * 32 + lhalf * 16;
            cpa16(d,                        pxh + ko);
            cpa16(d + 16,                   pxh + ko + 8);
            cpa16(d +     128 * ASTR2,      pxl + ko);
            cpa16(d +     128 * ASTR2 + 16, pxl + ko + 8);
            cpa16(d + 2 * 128 * ASTR2,      pwh + ko);
            cpa16(d + 2 * 128 * ASTR2 + 16, pwh + ko + 8);
            cpa16(d + 3 * 128 * ASTR2,      pwl + ko);
            cpa16(d + 3 * 128 * ASTR2 + 16, pwl + ko + 8);
            cpa_commit();
        };

        commit_stage(0, 0);

        for (int kts = 0; kts < 16; kts++) {
            asm volatile("cp.async.wait_group 0;");
            __syncthreads();
            if (kts + 1 < 16) commit_stage((kts + 1) & 1, kts + 1);

            const uint32_t po = (kts & 1) * STAGE2;
#pragma unroll
            for (int kk = 0; kk < 2; kk++) {
                const uint32_t kko = po + kk * 32;
                uint32_t ah[4][4], al[4][4], bh[4][2], bl[4][2];
#pragma unroll
                for (int mi = 0; mi < 4; mi++) {
                    ldsm_x4(ah[mi][0], ah[mi][1], ah[mi][2], ah[mi][3],
                            aAh0 + kko + mi * 16 * ASTR2);
                    ldsm_x4(al[mi][0], al[mi][1], al[mi][2], al[mi][3],
                            aAl0 + kko + mi * 16 * ASTR2);
                }
#pragma unroll
                for (int bg = 0; bg < 2; bg++) {
                    ldsm_x4(bh[2 * bg][0], bh[2 * bg][1], bh[2 * bg + 1][0], bh[2 * bg + 1][1],
                            aBh0 + kko + bg * 16 * ASTR2);
                    ldsm_x4(bl[2 * bg][0], bl[2 * bg][1], bl[2 * bg + 1][0], bl[2 * bg + 1][1],
                            aBl0 + kko + bg * 16 * ASTR2);
                }
#pragma unroll
                for (int mi = 0; mi < 4; mi++)
#pragma unroll
                    for (int ni = 0; ni < 4; ni++) {
                        mma16816(acc[mi][ni], ah[mi], bh[ni][0], bh[ni][1]);
                        mma16816(acc[mi][ni], ah[mi], bl[ni][0], bl[ni][1]);
                        mma16816(acc[mi][ni], al[mi], bh[ni][0], bh[ni][1]);
                    }
            }
        }

#pragma unroll
        for (int ni = 0; ni < 4; ni++) {
            const int n = n0 + wn * 32 + ni * 8 + 2 * (lane & 3);
            float b0 = bi[n], b1 = bi[n + 1];
#pragma unroll
            for (int mi = 0; mi < 4; mi++) {
                const int mm = m0 + wm * 64 + mi * 16 + (lane >> 2);
                float* C0 = g_pi + (size_t)mm * SIXH + n;
                float* C1 = g_pi + (size_t)(mm + 8) * SIXH + n;
                *(float2*)C0 = make_float2(acc[mi][ni][0] + b0, acc[mi][ni][1] + b1);
                *(float2*)C1 = make_float2(acc[mi][ni][2] + b0, acc[mi][ni][3] + b1);
            }
        }
        __threadfence();
        __syncthreads();
        if (tid == 0) atomicAdd(&g_piprog[mt], 1u);
        return;
    }

    // =================== persistent scan ===================
    __nv_bfloat16* sWh   = (__nv_bfloat16*)smc;          // NROW x SSTR
    __nv_bfloat16* sWl   = sWh + NROW * SSTR;            // NROW x SSTR
    float*         sPart = (float*)(sWl + NROW * SSTR);  // 8 x 16 x PSTR

    const int blk   = blockIdx.x;
    const int group = blk >> 6;
    const int cb    = blk & 63;
    const int sub   = cb >> 3;
    const int kh    = warp;

    // Ws -> smem bf16 split
    for (int i = tid; i < NROW * (H_ / 8); i += NTHR) {
        int l  = i >> 6;
        int d8 = (i & 63) << 3;
        __nv_bfloat16* ph = sWh + l * SSTR + d8;
        __nv_bfloat16* pl = sWl + l * SSTR + d8;
        int row = (l >> 3) * H_ + cb * CPB + (l & 7);
        const float* p = Ws + (size_t)row * H_ + d8;
#pragma unroll
        for (int q = 0; q < 8; q++) {
            float f = p[q];
            __nv_bfloat16 hh = __float2bfloat16(f);
            ph[q] = hh;
            pl[q] = __float2bfloat16(f - __bfloat162float(hh));
        }
    }

    const uint32_t aBh = (uint32_t)__cvta_generic_to_shared(
        sWh + (size_t)(lane & 7) * SSTR) + ((lane >> 3) & 1) * 16 + kh * 128;
    const uint32_t aBl = aBh + NROW * SSTR * 2;

    float c_reg = 0.f, h_reg = 0.f;
    float bsv[5] = {0.f, 0.f, 0.f, 0.f, 0.f};
    int bg = 0, j0 = 0, len = 0, b_local = 0, fo = 0;
    if (tid < 128) {
        b_local = tid >> 3;
        bg = group * BGRP + b_local;
        j0 = cb * CPB + (tid & 7);
        len = lengths[bg];
#pragma unroll
        for (int g = 0; g < 5; g++) bsv[g] = bs[g * H_ + j0];
        {
            const int c    = j0;
            const int frag = ((c >> 3) & 1) * 2 + (b_local >> 3);
            const int ln   = ((b_local & 7) << 2) | ((c >> 1) & 3);
            const int word = (((c >> 6) * 4 + ((c >> 4) & 3)) * 4 + frag) * 32 + ln;
            fo = word * 2 + (c & 1);
        }
        __stcg((unsigned short*)g_hfrag[0][0][group] + fo, (unsigned short)0);
        __stcg((unsigned short*)g_hfrag[1][0][group] + fo, (unsigned short)0);
        __threadfence();
    }
    __syncthreads();
    if (tid == 0) atomicAdd(&g_cnt[group][sub], 1u);

    const volatile unsigned* cptr = &g_cnt[group][kh];

    float pv_cur[6] = {0,0,0,0,0,0}, pv_nxt[6] = {0,0,0,0,0,0};
    const float* ppi = (tid < 128) ? g_pi + (size_t)bg * SIXH + j0 : g_pi;  // row t*32+bg
    if (tid < 128) {
        wait_pi(0);
#pragma unroll
        for (int g = 0; g < 6; g++) pv_cur[g] = ldcgf(ppi + g * H_);
    }

    for (int t = 0; t < T_; t++) {
        if (tid < 128 && t + 1 < T_) {
            if (((t + 1) & 3) == 0) wait_pi((t + 1) >> 2);
            const float* pp = ppi + (size_t)(t + 1) * (32 * SIXH);
#pragma unroll
            for (int g = 0; g < 6; g++) pv_nxt[g] = ldcgf(pp + g * H_);
        }

        if (lane == 0) {
            while (*cptr < 8u * (unsigned)(t + 1)) {}
        }
        __syncwarp();

        // A fragments (h) from fragment-ordered global buffer
        const uint32_t* bh_ = &g_hfrag[0][t & 1][group][kh * 512 + lane];
        const uint32_t* bl_ = &g_hfrag[1][t & 1][group][kh * 512 + lane];
        uint32_t Ah[4][4], Al[4][4];
#pragma unroll
        for (int kk = 0; kk < 4; kk++)
#pragma unroll
            for (int fr = 0; fr < 4; fr++) {
                Ah[kk][fr] = ldcg32(bh_ + (kk * 4 + fr) * 32);
                Al[kk][fr] = ldcg32(bl_ + (kk * 4 + fr) * 32);
            }

        {
            float acc[5][4];
#pragma unroll
            for (int ni = 0; ni < 5; ni++)
#pragma unroll
                for (int e = 0; e < 4; e++) acc[ni][e] = 0.f;
#pragma unroll
            for (int kk = 0; kk < 4; kk++) {
                const uint32_t ko = kk * 32;
#pragma unroll
                for (int ni = 0; ni < 5; ni++) {
                    const uint32_t bo = ko + ni * 8 * SSTR * 2;
                    uint32_t b0h, b1h, b0l, b1l;
                    ldsm_x2(b0h, b1h, aBh + bo);
                    ldsm_x2(b0l, b1l, aBl + bo);
                    mma16816(acc[ni], Ah[kk], b0h, b1h);
                    mma16816(acc[ni], Al[kk], b0h, b1h);
                    mma16816(acc[ni], Ah[kk], b0l, b1l);
                }
            }
            float* pp = sPart + kh * 16 * PSTR;
            const int r = lane >> 2;
#pragma unroll
            for (int ni = 0; ni < 5; ni++) {
                const int n = ni * 8 + 2 * (lane & 3);
                *(float2*)&pp[r * PSTR + n]       = make_float2(acc[ni][0], acc[ni][1]);
                *(float2*)&pp[(r + 8) * PSTR + n] = make_float2(acc[ni][2], acc[ni][3]);
            }
        }
        __syncthreads();

        if (tid < 128) {
            const int jj = tid & 7;
            float ps[5];
#pragma unroll
            for (int g = 0; g < 5; g++) {
                float s = 0.f;
#pragma unroll
                for (int w = 0; w < 8; w++)
                    s += sPart[w * 16 * PSTR + b_local * PSTR + g * 8 + jj];
                ps[g] = s + bsv[g];
            }
            float iv = sigm(pv_cur[0] + ps[0]);
            float fv = sigm(pv_cur[1] + ps[1]);
            float gv = tanh_(pv_cur[2] + ps[2]);
            float ov = sigm(pv_cur[3] + ps[3]);
            float cn = iv * gv + fv * c_reg;
            float o1 = ov * tanh_(cn);
            float rv = sigm(pv_cur[4] + ps[4]);
            float o2 = rv * o1 + (1.f - rv) * pv_cur[5];
            bool  m  = (t < len);
            h_reg = m ? o2 : h_reg;
            c_reg = m ? cn : c_reg;
            __nv_bfloat16 hh = __float2bfloat16(h_reg);
            __nv_bfloat16 hl = __float2bfloat16(h_reg - __bfloat162float(hh));
            const int par = (t + 1) & 1;
            __stcg((unsigned short*)g_hfrag[0][par][group] + fo, __bfloat16_as_ushort(hh));
            __stcg((unsigned short*)g_hfrag[1][par][group] + fo, __bfloat16_as_ushort(hl));
            out[((size_t)bg * T_ + t) * H_ + j0] = m ? o2 : 0.f;
            if (t == T_ - 1) {
                out[(size_t)B_ * T_ * H_ + bg * H_ + j0]      = h_reg;
                out[(size_t)B_ * T_ * H_ + BH + bg * H_ + j0] = c_reg;
            }
            __threadfence();
        }
#pragma unroll
        for (int g = 0; g < 6; g++) pv_cur[g] = pv_nxt[g];

        __syncthreads();
        if (tid == 0) atomicAdd(&g_cnt[group][sub], 1u);
    }
}

// ---------------------------------------------------------------------------
extern "C" void kernel_launch(void* const* d_in, const int* in_sizes, int n_in,
                              void* d_out, int out_size) {
    const float* x       = (const float*)d_in[0];
    const int*   lengths = (const int*)  d_in[1];
    const float* Wi      = (const float*)d_in[2];
    const float* bi      = (const float*)d_in[3];
    const float* Ws      = (const float*)d_in[4];
    const float* bs      = (const float*)d_in[5];
    float* out = (float*)d_out;

    const int smem = 2 * NROW * SSTR * 2 + 8 * 16 * PSTR * 4;   // 105,728 B
    cudaFuncSetAttribute(fused_k, cudaFuncAttributeMaxDynamicSharedMemorySize, smem);

    split_all_k<<<(NX4 + NW4 + 255) / 256, 256>>>(x, Wi);
    fused_k<<<NBLK + GTILES, NTHR, smem>>>(bi, Ws, bs, lengths, out);
}

// round 17
// speedup vs baseline: 2.0658x; 1.0907x over previous
#include <cuda_runtime.h>
#include <cuda_bf16.h>
#include <cstdint>
#include <cstddef>

#define B_   32
#define T_   512
#define H_   512
#define D_   512
#define SIXH 3072
#define BH   (B_ * H_)

#define NBLK 128
#define CPB  8
#define BGRP 16
#define NROW 40
#define SSTR 520
#define PSTR 44
#define NTHR 256
#define GTILES 3072          // 128 m-tiles x 24 n-tiles
#define NX4 ((B_ * T_ * D_) / 4)
#define NW4 ((SIXH * D_) / 4)

// Scratch (device globals)
__device__ float         g_pi[(size_t)B_ * T_ * SIXH];     // rows m = t*32 + b
__device__ uint32_t      g_hfrag[2][2][2][4096];
__device__ unsigned      g_cnt[2][8];
__device__ unsigned      g_piprog[128];                    // n-tiles done per m-tile
__device__ __nv_bfloat16 g_xhi[(size_t)B_ * T_ * D_];
__device__ __nv_bfloat16 g_xlo[(size_t)B_ * T_ * D_];
__device__ __nv_bfloat16 g_whi[(size_t)SIXH * D_];
__device__ __nv_bfloat16 g_wlo[(size_t)SIXH * D_];

__global__ void init_k() {
    int i = threadIdx.x;
    if (i < 128) g_piprog[i] = 0u;
    if (i < 16) ((unsigned*)g_cnt)[i] = 0u;
}

// ---------------------------------------------------------------------------
__global__ void split_k(const float* __restrict__ src,
                        __nv_bfloat16* __restrict__ hi,
                        __nv_bfloat16* __restrict__ lo, int n4) {
    int i = blockIdx.x * blockDim.x + threadIdx.x;
    if (i >= n4) return;
    float4 f = ((const float4*)src)[i];
    __nv_bfloat16 h0 = __float2bfloat16(f.x);
    __nv_bfloat16 h1 = __float2bfloat16(f.y);
    __nv_bfloat16 h2 = __float2bfloat16(f.z);
    __nv_bfloat16 h3 = __float2bfloat16(f.w);
    __nv_bfloat162 hv0, hv1, lv0, lv1;
    hv0.x = h0; hv0.y = h1; hv1.x = h2; hv1.y = h3;
    lv0.x = __float2bfloat16(f.x - __bfloat162float(h0));
    lv0.y = __float2bfloat16(f.y - __bfloat162float(h1));
    lv1.x = __float2bfloat16(f.z - __bfloat162float(h2));
    lv1.y = __float2bfloat16(f.w - __bfloat162float(h3));
    ((__nv_bfloat162*)hi)[2 * i]     = hv0;
    ((__nv_bfloat162*)hi)[2 * i + 1] = hv1;
    ((__nv_bfloat162*)lo)[2 * i]     = lv0;
    ((__nv_bfloat162*)lo)[2 * i + 1] = lv1;
}

// ---------------------------------------------------------------------------
__device__ __forceinline__ void ldsm_x4(uint32_t& r0, uint32_t& r1,
                                        uint32_t& r2, uint32_t& r3, uint32_t a) {
    asm volatile("ldmatrix.sync.aligned.m8n8.x4.shared.b16 {%0,%1,%2,%3}, [%4];"
                 : "=r"(r0), "=r"(r1), "=r"(r2), "=r"(r3) : "r"(a));
}
__device__ __forceinline__ void ldsm_x2(uint32_t& r0, uint32_t& r1, uint32_t a) {
    asm volatile("ldmatrix.sync.aligned.m8n8.x2.shared.b16 {%0,%1}, [%2];"
                 : "=r"(r0), "=r"(r1) : "r"(a));
}
__device__ __forceinline__ void mma16816(float* c, const uint32_t* a,
                                         uint32_t b0, uint32_t b1) {
    asm volatile(
        "mma.sync.aligned.m16n8k16.row.col.f32.bf16.bf16.f32 "
        "{%0,%1,%2,%3},{%4,%5,%6,%7},{%8,%9},{%0,%1,%2,%3};"
        : "+f"(c[0]), "+f"(c[1]), "+f"(c[2]), "+f"(c[3])
        : "r"(a[0]), "r"(a[1]), "r"(a[2]), "r"(a[3]), "r"(b0), "r"(b1));
}
__device__ __forceinline__ void cpa16(uint32_t dst, const void* src) {
    asm volatile("cp.async.cg.shared.global [%0], [%1], 16;"
                 :: "r"(dst), "l"(src));
}
__device__ __forceinline__ void cpa_commit() {
    asm volatile("cp.async.commit_group;");
}
__device__ __forceinline__ uint32_t ldcg32(const void* p) {
    uint32_t v;
    asm volatile("ld.global.cg.b32 %0, [%1];" : "=r"(v) : "l"(p));
    return v;
}
__device__ __forceinline__ float ldcgf(const float* p) {
    float v;
    asm volatile("ld.global.cg.f32 %0, [%1];" : "=f"(v) : "l"(p));
    return v;
}

__device__ __forceinline__ float sigm(float x)  { return 1.f / (1.f + __expf(-x)); }
__device__ __forceinline__ float tanh_(float x) { return 1.f - 2.f / (__expf(2.f * x) + 1.f); }

__device__ __forceinline__ void wait_pi(int mt) {
    if ((threadIdx.x & 31) == 0) {
        while (*(volatile unsigned*)&g_piprog[mt] < 24u) __nanosleep(64);
    }
    __syncwarp();
}

// ---------------------------------------------------------------------------
// Fused kernel: [0,128) persistent scan; [128, 128+3072) GEMM tiles.
// Scan truncates at its group's max sequence length.
// ---------------------------------------------------------------------------
#define ASTR2  80
#define STAGE2 (4 * 128 * ASTR2)   // 40960 B per stage (2 stages = 81920)

__global__ __launch_bounds__(256, 2) void fused_k(
    const float* __restrict__ bi, const float* __restrict__ Ws,
    const float* __restrict__ bs, const int* __restrict__ lengths,
    float* __restrict__ out)
{
    extern __shared__ char smc[];
    const int tid  = threadIdx.x;
    const int lane = tid & 31;
    const int warp = tid >> 5;

    if (blockIdx.x >= NBLK) {
        // =================== GEMM tile ===================
        const int g   = blockIdx.x - NBLK;
        const int mt  = g / 24;
        const int nt  = g - mt * 24;
        const int m0  = mt * 128;
        const int n0  = nt * 128;

        const int wm = warp >> 2;
        const int wn = warp & 3;

        const int lrow  = tid >> 1;
        const int lhalf = tid & 1;
        const int m     = m0 + lrow;
        const int xrow  = (m & 31) * T_ + (m >> 5);    // x[b][t] source row
        const __nv_bfloat16* pxh = g_xhi + (size_t)xrow * D_;
        const __nv_bfloat16* pxl = g_xlo + (size_t)xrow * D_;
        const __nv_bfloat16* pwh = g_whi + (size_t)(n0 + lrow) * D_;
        const __nv_bfloat16* pwl = g_wlo + (size_t)(n0 + lrow) * D_;

        const uint32_t sbase = (uint32_t)__cvta_generic_to_shared(smc);
        const uint32_t stoff = lrow * ASTR2 + lhalf * 32;

        const int rowA = wm * 64 + (lane & 15);
        const uint32_t aAh0 = sbase + rowA * ASTR2 + (lane >> 4) * 16;
        const uint32_t aAl0 = aAh0 + 128 * ASTR2;
        const int rowB = wn * 32 + (lane & 7) + ((lane >> 4) << 3);
        const uint32_t aBh0 = sbase + 2 * 128 * ASTR2 + rowB * ASTR2 + ((lane >> 3) & 1) * 16;
        const uint32_t aBl0 = aBh0 + 128 * ASTR2;

        float acc[4][4][4];
#pragma unroll
        for (int i = 0; i < 4; i++)
#pragma unroll
            for (int j = 0; j < 4; j++)
#pragma unroll
                for (int e = 0; e < 4; e++) acc[i][j][e] = 0.f;

        auto commit_stage = [&](int p, int kts) {
            uint32_t d = sbase + p * STAGE2 + stoff;
            const int ko = kts * 32 + lhalf * 16;
            cpa16(d,                        pxh + ko);
            cpa16(d + 16,                   pxh + ko + 8);
            cpa16(d +     128 * ASTR2,      pxl + ko);
            cpa16(d +     128 * ASTR2 + 16, pxl + ko + 8);
            cpa16(d + 2 * 128 * ASTR2,      pwh + ko);
            cpa16(d + 2 * 128 * ASTR2 + 16, pwh + ko + 8);
            cpa16(d + 3 * 128 * ASTR2,      pwl + ko);
            cpa16(d + 3 * 128 * ASTR2 + 16, pwl + ko + 8);
            cpa_commit();
        };

        commit_stage(0, 0);

        for (int kts = 0; kts < 16; kts++) {
            asm volatile("cp.async.wait_group 0;");
            __syncthreads();
            if (kts + 1 < 16) commit_stage((kts + 1) & 1, kts + 1);

            const uint32_t po = (kts & 1) * STAGE2;
#pragma unroll
            for (int kk = 0; kk < 2; kk++) {
                const uint32_t kko = po + kk * 32;
                uint32_t ah[4][4], al[4][4], bh[4][2], bl[4][2];
#pragma unroll
                for (int mi = 0; mi < 4; mi++) {
                    ldsm_x4(ah[mi][0], ah[mi][1], ah[mi][2], ah[mi][3],
                            aAh0 + kko + mi * 16 * ASTR2);
                    ldsm_x4(al[mi][0], al[mi][1], al[mi][2], al[mi][3],
                            aAl0 + kko + mi * 16 * ASTR2);
                }
#pragma unroll
                for (int bg = 0; bg < 2; bg++) {
                    ldsm_x4(bh[2 * bg][0], bh[2 * bg][1], bh[2 * bg + 1][0], bh[2 * bg + 1][1],
                            aBh0 + kko + bg * 16 * ASTR2);
                    ldsm_x4(bl[2 * bg][0], bl[2 * bg][1], bl[2 * bg + 1][0], bl[2 * bg + 1][1],
                            aBl0 + kko + bg * 16 * ASTR2);
                }
#pragma unroll
                for (int mi = 0; mi < 4; mi++)
#pragma unroll
                    for (int ni = 0; ni < 4; ni++) {
                        mma16816(acc[mi][ni], ah[mi], bh[ni][0], bh[ni][1]);
                        mma16816(acc[mi][ni], ah[mi], bl[ni][0], bl[ni][1]);
                        mma16816(acc[mi][ni], al[mi], bh[ni][0], bh[ni][1]);
                    }
            }
        }

#pragma unroll
        for (int ni = 0; ni < 4; ni++) {
            const int n = n0 + wn * 32 + ni * 8 + 2 * (lane & 3);
            float b0 = bi[n], b1 = bi[n + 1];
#pragma unroll
            for (int mi = 0; mi < 4; mi++) {
                const int mm = m0 + wm * 64 + mi * 16 + (lane >> 2);
                float* C0 = g_pi + (size_t)mm * SIXH + n;
                float* C1 = g_pi + (size_t)(mm + 8) * SIXH + n;
                *(float2*)C0 = make_float2(acc[mi][ni][0] + b0, acc[mi][ni][1] + b1);
                *(float2*)C1 = make_float2(acc[mi][ni][2] + b0, acc[mi][ni][3] + b1);
            }
        }
        __threadfence();
        __syncthreads();
        if (tid == 0) atomicAdd(&g_piprog[mt], 1u);
        return;
    }

    // =================== persistent scan ===================
    __nv_bfloat16* sWh   = (__nv_bfloat16*)smc;          // NROW x SSTR
    __nv_bfloat16* sWl   = sWh + NROW * SSTR;            // NROW x SSTR
    float*         sPart = (float*)(sWl + NROW * SSTR);  // 8 x 16 x PSTR

    const int blk   = blockIdx.x;
    const int group = blk >> 6;
    const int cb    = blk & 63;
    const int sub   = cb >> 3;
    const int kh    = warp;

    // Group max length (all threads compute identically; 16 cached LDG)
    int maxl = 1;
#pragma unroll
    for (int i = 0; i < BGRP; i++) {
        int l = __ldg(lengths + group * BGRP + i);
        maxl = l > maxl ? l : maxl;
    }

    // Ws -> smem bf16 split
    for (int i = tid; i < NROW * (H_ / 8); i += NTHR) {
        int l  = i >> 6;
        int d8 = (i & 63) << 3;
        __nv_bfloat16* ph = sWh + l * SSTR + d8;
        __nv_bfloat16* pl = sWl + l * SSTR + d8;
        int row = (l >> 3) * H_ + cb * CPB + (l & 7);
        const float* p = Ws + (size_t)row * H_ + d8;
#pragma unroll
        for (int q = 0; q < 8; q++) {
            float f = p[q];
            __nv_bfloat16 hh = __float2bfloat16(f);
            ph[q] = hh;
            pl[q] = __float2bfloat16(f - __bfloat162float(hh));
        }
    }

    const uint32_t aBh = (uint32_t)__cvta_generic_to_shared(
        sWh + (size_t)(lane & 7) * SSTR) + ((lane >> 3) & 1) * 16 + kh * 128;
    const uint32_t aBl = aBh + NROW * SSTR * 2;

    float c_reg = 0.f, h_reg = 0.f;
    float bsv[5] = {0.f, 0.f, 0.f, 0.f, 0.f};
    int bg = 0, j0 = 0, len = 0, b_local = 0, fo = 0;
    if (tid < 128) {
        b_local = tid >> 3;
        bg = group * BGRP + b_local;
        j0 = cb * CPB + (tid & 7);
        len = lengths[bg];
#pragma unroll
        for (int g = 0; g < 5; g++) bsv[g] = bs[g * H_ + j0];
        {
            const int c    = j0;
            const int frag = ((c >> 3) & 1) * 2 + (b_local >> 3);
            const int ln   = ((b_local & 7) << 2) | ((c >> 1) & 3);
            const int word = (((c >> 6) * 4 + ((c >> 4) & 3)) * 4 + frag) * 32 + ln;
            fo = word * 2 + (c & 1);
        }
        __stcg((unsigned short*)g_hfrag[0][0][group] + fo, (unsigned short)0);
        __stcg((unsigned short*)g_hfrag[1][0][group] + fo, (unsigned short)0);
        __threadfence();
    }
    __syncthreads();
    if (tid == 0) atomicAdd(&g_cnt[group][sub], 1u);

    const volatile unsigned* cptr = &g_cnt[group][kh];

    float pv_cur[6] = {0,0,0,0,0,0}, pv_nxt[6] = {0,0,0,0,0,0};
    const float* ppi = (tid < 128) ? g_pi + (size_t)bg * SIXH + j0 : g_pi;  // row t*32+bg
    if (tid < 128) {
        wait_pi(0);
#pragma unroll
        for (int g = 0; g < 6; g++) pv_cur[g] = ldcgf(ppi + g * H_);
    }

    for (int t = 0; t < maxl; t++) {
        if (tid < 128 && t + 1 < maxl) {
            if (((t + 1) & 3) == 0) wait_pi((t + 1) >> 2);
            const float* pp = ppi + (size_t)(t + 1) * (32 * SIXH);
#pragma unroll
            for (int g = 0; g < 6; g++) pv_nxt[g] = ldcgf(pp + g * H_);
        }

        if (lane == 0) {
            while (*cptr < 8u * (unsigned)(t + 1)) {}
        }
        __syncwarp();

        // A fragments (h) from fragment-ordered global buffer
        const uint32_t* bh_ = &g_hfrag[0][t & 1][group][kh * 512 + lane];
        const uint32_t* bl_ = &g_hfrag[1][t & 1][group][kh * 512 + lane];
        uint32_t Ah[4][4], Al[4][4];
#pragma unroll
        for (int kk = 0; kk < 4; kk++)
#pragma unroll
            for (int fr = 0; fr < 4; fr++) {
                Ah[kk][fr] = ldcg32(bh_ + (kk * 4 + fr) * 32);
                Al[kk][fr] = ldcg32(bl_ + (kk * 4 + fr) * 32);
            }

        {
            float acc[5][4];
#pragma unroll
            for (int ni = 0; ni < 5; ni++)
#pragma unroll
                for (int e = 0; e < 4; e++) acc[ni][e] = 0.f;
#pragma unroll
            for (int kk = 0; kk < 4; kk++) {
                const uint32_t ko = kk * 32;
#pragma unroll
                for (int ni = 0; ni < 5; ni++) {
                    const uint32_t bo = ko + ni * 8 * SSTR * 2;
                    uint32_t b0h, b1h, b0l, b1l;
                    ldsm_x2(b0h, b1h, aBh + bo);
                    ldsm_x2(b0l, b1l, aBl + bo);
                    mma16816(acc[ni], Ah[kk], b0h, b1h);
                    mma16816(acc[ni], Al[kk], b0h, b1h);
                    mma16816(acc[ni], Ah[kk], b0l, b1l);
                }
            }
            float* pp = sPart + kh * 16 * PSTR;
            const int r = lane >> 2;
#pragma unroll
            for (int ni = 0; ni < 5; ni++) {
                const int n = ni * 8 + 2 * (lane & 3);
                *(float2*)&pp[r * PSTR + n]       = make_float2(acc[ni][0], acc[ni][1]);
                *(float2*)&pp[(r + 8) * PSTR + n] = make_float2(acc[ni][2], acc[ni][3]);
            }
        }
        __syncthreads();

        if (tid < 128) {
            const int jj = tid & 7;
            float ps[5];
#pragma unroll
            for (int g = 0; g < 5; g++) {
                float s = 0.f;
#pragma unroll
                for (int w = 0; w < 8; w++)
                    s += sPart[w * 16 * PSTR + b_local * PSTR + g * 8 + jj];
                ps[g] = s + bsv[g];
            }
            float iv = sigm(pv_cur[0] + ps[0]);
            float fv = sigm(pv_cur[1] + ps[1]);
            float gv = tanh_(pv_cur[2] + ps[2]);
            float ov = sigm(pv_cur[3] + ps[3]);
            float cn = iv * gv + fv * c_reg;
            float o1 = ov * tanh_(cn);
            float rv = sigm(pv_cur[4] + ps[4]);
            float o2 = rv * o1 + (1.f - rv) * pv_cur[5];
            bool  m  = (t < len);
            h_reg = m ? o2 : h_reg;
            c_reg = m ? cn : c_reg;
            __nv_bfloat16 hh = __float2bfloat16(h_reg);
            __nv_bfloat16 hl = __float2bfloat16(h_reg - __bfloat162float(hh));
            const int par = (t + 1) & 1;
            __stcg((unsigned short*)g_hfrag[0][par][group] + fo, __bfloat16_as_ushort(hh));
            __stcg((unsigned short*)g_hfrag[1][par][group] + fo, __bfloat16_as_ushort(hl));
            out[((size_t)bg * T_ + t) * H_ + j0] = m ? o2 : 0.f;
            __threadfence();
        }
#pragma unroll
        for (int g = 0; g < 6; g++) pv_cur[g] = pv_nxt[g];

        __syncthreads();
        if (tid == 0) atomicAdd(&g_cnt[group][sub], 1u);
    }

    // Epilogue: zero tail rows [maxl, T) and write hT/cT (state frozen past len).
    if (tid < 128) {
        for (int t = maxl; t < T_; t++)
            out[((size_t)bg * T_ + t) * H_ + j0] = 0.f;
        out[(size_t)B_ * T_ * H_ + bg * H_ + j0]      = h_reg;
        out[(size_t)B_ * T_ * H_ + BH + bg * H_ + j0] = c_reg;
    }
}

// ---------------------------------------------------------------------------
extern "C" void kernel_launch(void* const* d_in, const int* in_sizes, int n_in,
                              void* d_out, int out_size) {
    const float* x       = (const float*)d_in[0];
    const int*   lengths = (const int*)  d_in[1];
    const float* Wi      = (const float*)d_in[2];
    const float* bi      = (const float*)d_in[3];
    const float* Ws      = (const float*)d_in[4];
    const float* bs      = (const float*)d_in[5];
    float* out = (float*)d_out;

    const int smem = 2 * NROW * SSTR * 2 + 8 * 16 * PSTR * 4;   // 105,728 B
    cudaFuncSetAttribute(fused_k, cudaFuncAttributeMaxDynamicSharedMemorySize, smem);

    init_k<<<1, 128>>>();

    __nv_bfloat16 *xhi, *xlo, *whi, *wlo;
    cudaGetSymbolAddress((void**)&xhi, g_xhi);
    cudaGetSymbolAddress((void**)&xlo, g_xlo);
    cudaGetSymbolAddress((void**)&whi, g_whi);
    cudaGetSymbolAddress((void**)&wlo, g_wlo);

    split_k<<<(NX4 + 255) / 256, 256>>>(x, xhi, xlo, NX4);
    split_k<<<(NW4 + 255) / 256, 256>>>(Wi, whi, wlo, NW4);

    fused_k<<<NBLK + GTILES, NTHR, smem>>>(bi, Ws, bs, lengths, out);
}